// round 3
// baseline (speedup 1.0000x reference)
#include <cuda_runtime.h>
#include <cuda_bf16.h>
#include <math.h>

// Problem constants (fixed by the reference)
#define NPTS   16384
#define MPTS   4096        // NPTS / STRIDE
#define KNN    16
#define DIN    64
#define DOUT   128

typedef unsigned long long ull;

// ---------------- device scratch (no allocations allowed) ----------------
__device__ float g_h[MPTS * DOUT];       // pre-BN linear output, 2MB
__device__ float g_scale[DOUT];
__device__ float g_shift[DOUT];

__device__ __forceinline__ float warpmaxf(float v) {
#pragma unroll
    for (int o = 16; o > 0; o >>= 1)
        v = fmaxf(v, __shfl_xor_sync(0xffffffffu, v, o));
    return v;
}

// Packed f32x2 helpers (rounding identical to scalar __fadd_rn/__fmul_rn)
__device__ __forceinline__ ull add2(ull a, ull b) {
    ull r; asm("add.rn.f32x2 %0, %1, %2;" : "=l"(r) : "l"(a), "l"(b)); return r;
}
__device__ __forceinline__ ull mul2(ull a, ull b) {
    ull r; asm("mul.rn.f32x2 %0, %1, %2;" : "=l"(r) : "l"(a), "l"(b)); return r;
}
__device__ __forceinline__ ull bcast2(float a) {
    ull r; asm("mov.b64 %0, {%1, %1};" : "=l"(r) : "f"(a)); return r;
}
__device__ __forceinline__ void unpack2(ull v, float& lo, float& hi) {
    asm("mov.b64 {%0, %1}, %2;" : "=f"(lo), "=f"(hi) : "l"(v));
}

// =====================================================================
// Kernel 1: Furthest Point Sampling. Single block, 1024 threads.
// Points in 192KB dynamic SMEM as SoA pair arrays (ull = 2 floats).
// Per-thread dmin[16] in registers. Distance in reference order
// (dx*dx + dy*dy) + dz*dz, no FMA contraction (f32x2 rn == scalar rn).
// Argmax tie-break = lowest index. 2 barriers per round.
// =====================================================================
__global__ __launch_bounds__(1024, 1)
void fps_kernel(const float* __restrict__ p, float* __restrict__ out)
{
    extern __shared__ ull sm[];
    ull* X2 = sm;               // 8192 pairs of x
    ull* Y2 = sm + 8192;
    ull* Z2 = sm + 16384;
    __shared__ unsigned s_val[2];
    __shared__ int      s_idx[2];

    const int t = threadIdx.x;
    float* Xf = (float*)X2;
    float* Yf = (float*)Y2;
    float* Zf = (float*)Z2;

#pragma unroll
    for (int k = 0; k < 16; k++) {
        int i = t + k * 1024;
        Xf[i] = p[3 * i + 0];
        Yf[i] = p[3 * i + 1];
        Zf[i] = p[3 * i + 2];
    }
    if (t == 0) {
        s_val[0] = 0u; s_val[1] = 0u;
        s_idx[0] = 0x7fffffff; s_idx[1] = 0x7fffffff;
    }
    __syncthreads();

    float dmin[16];
#pragma unroll
    for (int k = 0; k < 16; k++) dmin[k] = 3.4e38f;

    float lx = Xf[0], ly = Yf[0], lz = Zf[0];
    if (t == 0) {
        out[0] = lx; out[1] = ly; out[2] = lz;
    }

    for (int i = 1; i < MPTS; i++) {
        const ull nlx = bcast2(-lx);
        const ull nly = bcast2(-ly);
        const ull nlz = bcast2(-lz);
        float bestv = -1.0f;
#pragma unroll
        for (int k = 0; k < 8; k++) {
            int j = t + k * 1024;
            ull dx = add2(X2[j], nlx);
            ull dy = add2(Y2[j], nly);
            ull dz = add2(Z2[j], nlz);
            // reference order: (dx*dx + dy*dy) + dz*dz
            ull s = add2(add2(mul2(dx, dx), mul2(dy, dy)), mul2(dz, dz));
            float d0, d1; unpack2(s, d0, d1);
            float m0 = fminf(dmin[2 * k + 0], d0); dmin[2 * k + 0] = m0;
            float m1 = fminf(dmin[2 * k + 1], d1); dmin[2 * k + 1] = m1;
            bestv = fmaxf(bestv, fmaxf(m0, m1));
        }
        // warp max (dmin >= 0 so float order == uint bit order)
        bestv = warpmaxf(bestv);
        const int slot = i & 1;
        if ((t & 31) == 0) atomicMax(&s_val[slot], __float_as_uint(bestv));
        __syncthreads();
        const unsigned vb = s_val[slot];
#pragma unroll
        for (int k = 0; k < 16; k++) {
            if (__float_as_uint(dmin[k]) == vb)
                atomicMin(&s_idx[slot], 2 * (t + (k >> 1) * 1024) + (k & 1));
        }
        if (t == 0) {   // reset other slot for round i+1 (safe: its last
            s_val[slot ^ 1] = 0u;            // reader passed the barrier above)
            s_idx[slot ^ 1] = 0x7fffffff;
        }
        __syncthreads();
        const int bi = s_idx[slot];
        lx = Xf[bi]; ly = Yf[bi]; lz = Zf[bi];
        if (t == 0) {
            out[3 * i + 0] = lx;
            out[3 * i + 1] = ly;
            out[3 * i + 2] = lz;
        }
    }
}

// =====================================================================
// Kernel 2: kNN + group + max-pool features + Linear  (one query/warp)
// Warp-distributed sorted top-16 list (lane l < 16 holds l-th smallest)
// with broadcast threshold tau; ballot-filtered inserts.
// =====================================================================
#define TILEPTS 2048

__global__ __launch_bounds__(256)
void knn_feat_kernel(const float* __restrict__ p,
                     const float* __restrict__ x,
                     const float* __restrict__ W,
                     const float* __restrict__ bias,
                     const float* __restrict__ out /* n_p at [0,3*MPTS) */)
{
    __shared__ float4 tile[TILEPTS];
    const int lane = threadIdx.x & 31;
    const int warp = threadIdx.x >> 5;
    const int q = blockIdx.x * 8 + warp;

    const float sx = out[3 * q + 0];
    const float sy = out[3 * q + 1];
    const float sz = out[3 * q + 2];
    // |s|^2 in reference order
    const float s2 = __fadd_rn(__fadd_rn(__fmul_rn(sx, sx), __fmul_rn(sy, sy)),
                               __fmul_rn(sz, sz));

    float kval = 3.4e38f;   // sorted ascending across lanes 0..15
    int   kidx = 0;
    float tau  = 3.4e38f;   // current 16th-best (lane 15), broadcast

    for (int t0 = 0; t0 < NPTS / TILEPTS; t0++) {
        __syncthreads();
        for (int j = threadIdx.x; j < TILEPTS; j += 256) {
            int g = t0 * TILEPTS + j;
            float a = p[3 * g + 0];
            float b = p[3 * g + 1];
            float c = p[3 * g + 2];
            float n2 = __fadd_rn(__fadd_rn(__fmul_rn(a, a), __fmul_rn(b, b)),
                                 __fmul_rn(c, c));
            tile[j] = make_float4(a, b, c, n2);
        }
        __syncthreads();

        for (int s = 0; s < TILEPTS / 32; s++) {
            float4 cd = tile[s * 32 + lane];
            // d2 = (|s|^2 + |p|^2) - 2*(s.p), reference-ordered
            float dot = __fadd_rn(__fadd_rn(__fmul_rn(sx, cd.x), __fmul_rn(sy, cd.y)),
                                  __fmul_rn(sz, cd.z));
            float key = __fsub_rn(__fadd_rn(s2, cd.w), __fmul_rn(2.0f, dot));

            unsigned mask = __ballot_sync(0xffffffffu, key < tau);
            while (mask) {
                int src = __ffs(mask) - 1;
                mask &= mask - 1;
                float v = __shfl_sync(0xffffffffu, key, src);
                if (v < tau) {
                    int id = t0 * TILEPTS + s * 32 + src;
                    bool ins = (lane < 16) && (v < kval);
                    float pv = __shfl_up_sync(0xffffffffu, kval, 1);
                    int   pi = __shfl_up_sync(0xffffffffu, kidx, 1);
                    int   pp = __shfl_up_sync(0xffffffffu, (int)ins, 1);
                    if (ins) {
                        bool useprev = (lane > 0) && pp;
                        kval = useprev ? pv : v;
                        kidx = useprev ? pi : id;
                    }
                    tau = __shfl_sync(0xffffffffu, kval, 15);
                }
            }
        }
    }

    // ---- grouping: relative coords, max-norm normalize, max-pool ----
    float pjx = -3.4e38f, pjy = -3.4e38f, pjz = -3.4e38f, nrm = -3.4e38f;
    if (lane < 16) {
        int nb = kidx;
        pjx = p[3 * nb + 0] - sx;
        pjy = p[3 * nb + 1] - sy;
        pjz = p[3 * nb + 2] - sz;
        nrm = sqrtf(fmaf(pjz, pjz, fmaf(pjy, pjy, pjx * pjx)));
    }
    float mx = warpmaxf(nrm);
    float denom = mx + 1e-8f;
    float f0 = warpmaxf(pjx) / denom;
    float f1 = warpmaxf(pjy) / denom;
    float f2 = warpmaxf(pjz) / denom;

    float fx0 = -3.4e38f, fx1 = -3.4e38f;
#pragma unroll
    for (int j = 0; j < KNN; j++) {
        int row = __shfl_sync(0xffffffffu, kidx, j);
        const float* xr = x + row * DIN;
        fx0 = fmaxf(fx0, xr[lane]);
        fx1 = fmaxf(fx1, xr[lane + 32]);
    }

    // ---- linear: h = feat @ W + b  (lane handles 4 output cols) ----
    const int c0 = lane, c1 = lane + 32, c2 = lane + 64, c3 = lane + 96;
    float a0 = bias[c0], a1 = bias[c1], a2 = bias[c2], a3 = bias[c3];
    {
        const float* w0 = W;               // row 0
        const float* w1 = W + DOUT;        // row 1
        const float* w2 = W + 2 * DOUT;    // row 2
        a0 = fmaf(f0, w0[c0], a0); a1 = fmaf(f0, w0[c1], a1);
        a2 = fmaf(f0, w0[c2], a2); a3 = fmaf(f0, w0[c3], a3);
        a0 = fmaf(f1, w1[c0], a0); a1 = fmaf(f1, w1[c1], a1);
        a2 = fmaf(f1, w1[c2], a2); a3 = fmaf(f1, w1[c3], a3);
        a0 = fmaf(f2, w2[c0], a0); a1 = fmaf(f2, w2[c1], a1);
        a2 = fmaf(f2, w2[c2], a2); a3 = fmaf(f2, w2[c3], a3);
    }
#pragma unroll
    for (int r = 0; r < DIN; r++) {
        float fr = (r < 32) ? __shfl_sync(0xffffffffu, fx0, r)
                            : __shfl_sync(0xffffffffu, fx1, r - 32);
        const float* wr = W + (r + 3) * DOUT;
        a0 = fmaf(fr, wr[c0], a0);
        a1 = fmaf(fr, wr[c1], a1);
        a2 = fmaf(fr, wr[c2], a2);
        a3 = fmaf(fr, wr[c3], a3);
    }
    float* hq = g_h + q * DOUT;
    hq[c0] = a0; hq[c1] = a1; hq[c2] = a2; hq[c3] = a3;
}

// =====================================================================
// Kernel 3: BatchNorm statistics, one block per output column.
// Deterministic two-pass reduction (bit-stable across replays).
// =====================================================================
__global__ __launch_bounds__(256)
void bn_stats_kernel(const float* __restrict__ gamma,
                     const float* __restrict__ beta)
{
    __shared__ float red[256];
    const int c = blockIdx.x;
    const int t = threadIdx.x;

    float s = 0.0f;
    for (int r = t; r < MPTS; r += 256) s += g_h[r * DOUT + c];
    red[t] = s;
    __syncthreads();
#pragma unroll
    for (int o = 128; o > 0; o >>= 1) {
        if (t < o) red[t] += red[t + o];
        __syncthreads();
    }
    float mean = red[0] * (1.0f / MPTS);
    __syncthreads();

    float s2 = 0.0f;
    for (int r = t; r < MPTS; r += 256) {
        float d = g_h[r * DOUT + c] - mean;
        s2 = fmaf(d, d, s2);
    }
    red[t] = s2;
    __syncthreads();
#pragma unroll
    for (int o = 128; o > 0; o >>= 1) {
        if (t < o) red[t] += red[t + o];
        __syncthreads();
    }
    if (t == 0) {
        float var = red[0] * (1.0f / MPTS);
        float sc = gamma[c] / sqrtf(var + 1e-5f);
        g_scale[c] = sc;
        g_shift[c] = beta[c] - mean * sc;
    }
}

// =====================================================================
// Kernel 4: normalize + ReLU + write x_out; write n_o tail
// =====================================================================
__global__ __launch_bounds__(256)
void finalize_kernel(float* __restrict__ out, int out_size)
{
    int i = blockIdx.x * 256 + threadIdx.x;
    if (i < MPTS * DOUT) {
        int c = i & (DOUT - 1);
        float v = fmaf(g_h[i], g_scale[c], g_shift[c]);
        out[3 * MPTS + i] = v > 0.0f ? v : 0.0f;
    }
    if (blockIdx.x == 0 && threadIdx.x == 0) {
        for (int j = 3 * MPTS + MPTS * DOUT; j < out_size; j++)
            out[j] = (float)MPTS;   // n_o = [M] cast to output dtype
    }
}

// =====================================================================
extern "C" void kernel_launch(void* const* d_in, const int* in_sizes, int n_in,
                              void* d_out, int out_size)
{
    const float* p     = (const float*)d_in[0];
    const float* x     = (const float*)d_in[1];
    // d_in[2] = o (offsets), unused for single cloud
    const float* W     = (const float*)d_in[3];
    const float* b     = (const float*)d_in[4];
    const float* gamma = (const float*)d_in[5];
    const float* beta  = (const float*)d_in[6];
    float* out = (float*)d_out;

    cudaFuncSetAttribute((const void*)fps_kernel,
                         cudaFuncAttributeMaxDynamicSharedMemorySize,
                         3 * NPTS * sizeof(float));

    fps_kernel<<<1, 1024, 3 * NPTS * sizeof(float)>>>(p, out);
    knn_feat_kernel<<<MPTS / 8, 256>>>(p, x, W, b, out);
    bn_stats_kernel<<<DOUT, 256>>>(gamma, beta);
    finalize_kernel<<<(MPTS * DOUT + 255) / 256, 256>>>(out, out_size);
}

// round 6
// speedup vs baseline: 1.1500x; 1.1500x over previous
#include <cuda_runtime.h>
#include <cuda_bf16.h>
#include <math.h>

// Problem constants (fixed by the reference)
#define NPTS   16384
#define MPTS   4096        // NPTS / STRIDE
#define KNN    16
#define DIN    64
#define DOUT   128

#define CHUNKS 256         // 64 points per chunk, 8 chunks per warp
#define FINF   3.402823466e38f

typedef unsigned long long ull;

// ---------------- device scratch (no allocations allowed) ----------------
__device__ float g_h[MPTS * DOUT];       // pre-BN linear output, 2MB
__device__ float g_scale[DOUT];
__device__ float g_shift[DOUT];

__device__ __forceinline__ float warpmaxf(float v) {
#pragma unroll
    for (int o = 16; o > 0; o >>= 1)
        v = fmaxf(v, __shfl_xor_sync(0xffffffffu, v, o));
    return v;
}

// =====================================================================
// Kernel 1: Furthest Point Sampling with exact geometric pruning.
// Single block, 1024 threads. Coords in SMEM at ORIGINAL indices.
// Points partitioned into 256 Morton-ordered chunks of 64; per-thread
// dmin[16] + packed member ids in registers. A chunk is skipped when
// dist^2(bbox, last) * (1-1e-5) >= chunk max dmin  -- provably a no-op
// on every dmin bit, so results are bit-identical to brute force and
// independent of the (nondeterministic) scatter order.
// Distance in reference order (dx*dx + dy*dy) + dz*dz, no FMA.
// Global argmax via 64-bit keys (valbits<<32 | (16383-id)):
// max value, ties -> lowest original index (jnp.argmax convention).
// =====================================================================
__global__ __launch_bounds__(1024, 1)
void fps_kernel(const float* __restrict__ p, float* __restrict__ out)
{
    extern __shared__ float sm[];
    float* X = sm;
    float* Y = sm + NPTS;
    float* Z = sm + 2 * NPTS;
    // alias region after coords (36KB):
    unsigned short* sid  = (unsigned short*)(sm + 3 * NPTS);     // 32KB (preproc only)
    int*            hist = (int*)(sm + 3 * NPTS + NPTS / 2);     // 2KB  (preproc only)
    float*          bbox = (float*)(sm + 3 * NPTS);              // 6KB  (aliases sid, after)

    __shared__ ull   s_best[3];
    __shared__ float s_part[32][6];
    __shared__ float s_bb[6];     // global bbox: mnx,mxx,mny,mxy,mnz,mxz

    const int t    = threadIdx.x;
    const int lane = t & 31;
    const int w    = t >> 5;

    // ---- load coords + global bbox ----
    float mnx = FINF, mxx = -FINF, mny = FINF, mxy = -FINF, mnz = FINF, mxz = -FINF;
#pragma unroll
    for (int k = 0; k < 16; k++) {
        int i = t + (k << 10);
        float a = p[3 * i + 0], b = p[3 * i + 1], c = p[3 * i + 2];
        X[i] = a; Y[i] = b; Z[i] = c;
        mnx = fminf(mnx, a); mxx = fmaxf(mxx, a);
        mny = fminf(mny, b); mxy = fmaxf(mxy, b);
        mnz = fminf(mnz, c); mxz = fmaxf(mxz, c);
    }
#pragma unroll
    for (int o = 16; o > 0; o >>= 1) {
        mnx = fminf(mnx, __shfl_xor_sync(~0u, mnx, o));
        mxx = fmaxf(mxx, __shfl_xor_sync(~0u, mxx, o));
        mny = fminf(mny, __shfl_xor_sync(~0u, mny, o));
        mxy = fmaxf(mxy, __shfl_xor_sync(~0u, mxy, o));
        mnz = fminf(mnz, __shfl_xor_sync(~0u, mnz, o));
        mxz = fmaxf(mxz, __shfl_xor_sync(~0u, mxz, o));
    }
    if (lane == 0) {
        s_part[w][0] = mnx; s_part[w][1] = mxx;
        s_part[w][2] = mny; s_part[w][3] = mxy;
        s_part[w][4] = mnz; s_part[w][5] = mxz;
    }
    if (t == 0) { s_best[0] = 0; s_best[1] = 0; s_best[2] = 0; }
    if (t < 512) hist[t] = 0;
    __syncthreads();
    if (t < 6) {
        float v = s_part[0][t];
        if (t & 1) { for (int j = 1; j < 32; j++) v = fmaxf(v, s_part[j][t]); }
        else       { for (int j = 1; j < 32; j++) v = fminf(v, s_part[j][t]); }
        s_bb[t] = v;
    }
    __syncthreads();

    // ---- Morton bucket (9-bit: 3 bits/dim) + counting sort ----
    const float scx = 8.0f / (s_bb[1] - s_bb[0] + 1e-5f);
    const float scy = 8.0f / (s_bb[3] - s_bb[2] + 1e-5f);
    const float scz = 8.0f / (s_bb[5] - s_bb[4] + 1e-5f);
    const float b0x = s_bb[0], b0y = s_bb[2], b0z = s_bb[4];

#pragma unroll
    for (int k = 0; k < 16; k++) {
        int i = t + (k << 10);
        int qx = min(7, (int)((X[i] - b0x) * scx));
        int qy = min(7, (int)((Y[i] - b0y) * scy));
        int qz = min(7, (int)((Z[i] - b0z) * scz));
        int bk = ((qx & 1) | ((qx & 2) << 2) | ((qx & 4) << 4))
               | (((qy & 1) | ((qy & 2) << 2) | ((qy & 4) << 4)) << 1)
               | (((qz & 1) | ((qz & 2) << 2) | ((qz & 4) << 4)) << 2);
        atomicAdd(&hist[bk], 1);
    }
    __syncthreads();
    if (t == 0) {                       // exclusive scan (one-time, cheap)
        int run = 0;
        for (int j = 0; j < 512; j++) { int c = hist[j]; hist[j] = run; run += c; }
    }
    __syncthreads();
#pragma unroll
    for (int k = 0; k < 16; k++) {
        int i = t + (k << 10);
        int qx = min(7, (int)((X[i] - b0x) * scx));
        int qy = min(7, (int)((Y[i] - b0y) * scy));
        int qz = min(7, (int)((Z[i] - b0z) * scz));
        int bk = ((qx & 1) | ((qx & 2) << 2) | ((qx & 4) << 4))
               | (((qy & 1) | ((qy & 2) << 2) | ((qy & 4) << 4)) << 1)
               | (((qz & 1) | ((qz & 2) << 2) | ((qz & 4) << 4)) << 2);
        int pos = atomicAdd(&hist[bk], 1);
        sid[pos] = (unsigned short)i;
    }
    __syncthreads();

    // ---- adopt chunk membership into registers ----
    unsigned ids[8];
    float dmin[16];
#pragma unroll
    for (int k = 0; k < 8; k++) {
        int base = (w * 8 + k) * 64;
        unsigned lo = sid[base + lane];
        unsigned hi = sid[base + 32 + lane];
        ids[k] = lo | (hi << 16);
        dmin[2 * k + 0] = FINF;
        dmin[2 * k + 1] = FINF;
    }
    __syncthreads();   // all sid reads done; alias region becomes bbox

    // ---- per-chunk bounding boxes ----
#pragma unroll
    for (int k = 0; k < 8; k++) {
        int c = w * 8 + k;
        int i0 = ids[k] & 0xffff, i1 = ids[k] >> 16;
        float x0 = X[i0], x1 = X[i1];
        float y0 = Y[i0], y1 = Y[i1];
        float z0 = Z[i0], z1 = Z[i1];
        float a = fminf(x0, x1), b = fmaxf(x0, x1);
        float c2 = fminf(y0, y1), d = fmaxf(y0, y1);
        float e = fminf(z0, z1), f = fmaxf(z0, z1);
#pragma unroll
        for (int o = 16; o > 0; o >>= 1) {
            a = fminf(a, __shfl_xor_sync(~0u, a, o));
            b = fmaxf(b, __shfl_xor_sync(~0u, b, o));
            c2 = fminf(c2, __shfl_xor_sync(~0u, c2, o));
            d = fmaxf(d, __shfl_xor_sync(~0u, d, o));
            e = fminf(e, __shfl_xor_sync(~0u, e, o));
            f = fmaxf(f, __shfl_xor_sync(~0u, f, o));
        }
        if (lane == 0) {
            bbox[6 * c + 0] = a; bbox[6 * c + 1] = b;
            bbox[6 * c + 2] = c2; bbox[6 * c + 3] = d;
            bbox[6 * c + 4] = e; bbox[6 * c + 5] = f;
        }
    }
    ull ckey = ((ull)0x7f800000u) << 32;   // lane k (<8) holds chunk k's key; val=+inf
    __syncthreads();

    // ---- main FPS loop: 1 barrier per round ----
    float lx = X[0], ly = Y[0], lz = Z[0];
    if (t == 0) { out[0] = lx; out[1] = ly; out[2] = lz; }

    int slot = 1;
    for (int i = 1; i < MPTS; i++) {
        // prune test: lane k (<8) checks chunk w*8+k
        bool sv = false;
        if (lane < 8) {
            const float* bb = &bbox[(w * 8 + lane) * 6];
            float ax = fmaxf(fmaxf(bb[0] - lx, lx - bb[1]), 0.0f);
            float ay = fmaxf(fmaxf(bb[2] - lx * 0.0f - ly, ly - bb[3]), 0.0f);
            float az = fmaxf(fmaxf(bb[4] - lz, lz - bb[5]), 0.0f);
            float lb = ax * ax + ay * ay + az * az;
            float maxv = __uint_as_float((unsigned)(ckey >> 32));
            sv = (lb * 0.99999f < maxv);
        }
        unsigned survive = __ballot_sync(~0u, sv) & 0xffu;

#pragma unroll
        for (int k = 0; k < 8; k++) {
            if (survive & (1u << k)) {
                int i0 = ids[k] & 0xffff, i1 = ids[k] >> 16;
                // reference-order distance, no FMA contraction
                float dx0 = __fsub_rn(X[i0], lx), dy0 = __fsub_rn(Y[i0], ly), dz0 = __fsub_rn(Z[i0], lz);
                float d0 = __fadd_rn(__fadd_rn(__fmul_rn(dx0, dx0), __fmul_rn(dy0, dy0)),
                                     __fmul_rn(dz0, dz0));
                float dx1 = __fsub_rn(X[i1], lx), dy1 = __fsub_rn(Y[i1], ly), dz1 = __fsub_rn(Z[i1], lz);
                float d1 = __fadd_rn(__fadd_rn(__fmul_rn(dx1, dx1), __fmul_rn(dy1, dy1)),
                                     __fmul_rn(dz1, dz1));
                float m0 = fminf(dmin[2 * k + 0], d0); dmin[2 * k + 0] = m0;
                float m1 = fminf(dmin[2 * k + 1], d1); dmin[2 * k + 1] = m1;
                ull k0 = (((ull)__float_as_uint(m0)) << 32) | (unsigned)(16383 - i0);
                ull k1 = (((ull)__float_as_uint(m1)) << 32) | (unsigned)(16383 - i1);
                ull m = k0 > k1 ? k0 : k1;
#pragma unroll
                for (int o = 16; o > 0; o >>= 1) {
                    ull q = __shfl_xor_sync(~0u, m, o);
                    m = q > m ? q : m;
                }
                if (lane == k) ckey = m;
            }
        }

        // warp best over its 8 chunks, then global via atomicMax
        ull wb = (lane < 8) ? ckey : 0ull;
#pragma unroll
        for (int o = 4; o > 0; o >>= 1) {
            ull q = __shfl_xor_sync(~0u, wb, o);
            wb = q > wb ? q : wb;
        }
        if (lane == 0) atomicMax(&s_best[slot], wb);
        int nslot = slot + 1; if (nslot == 3) nslot = 0;
        if (t == 0) s_best[nslot] = 0;   // readers/writers of nslot are >=2 barriers away
        __syncthreads();
        ull g = s_best[slot];
        int bi = 16383 - (int)(g & 0xffffffffu);
        lx = X[bi]; ly = Y[bi]; lz = Z[bi];
        if (t == 0) {
            out[3 * i + 0] = lx;
            out[3 * i + 1] = ly;
            out[3 * i + 2] = lz;
        }
        slot = nslot;
    }
}

// =====================================================================
// Kernel 2: kNN + group + max-pool features + Linear  (one query/warp)
// =====================================================================
#define TILEPTS 2048

__global__ __launch_bounds__(256)
void knn_feat_kernel(const float* __restrict__ p,
                     const float* __restrict__ x,
                     const float* __restrict__ W,
                     const float* __restrict__ bias,
                     const float* __restrict__ out /* n_p at [0,3*MPTS) */)
{
    __shared__ float4 tile[TILEPTS];
    const int lane = threadIdx.x & 31;
    const int warp = threadIdx.x >> 5;
    const int q = blockIdx.x * 8 + warp;

    const float sx = out[3 * q + 0];
    const float sy = out[3 * q + 1];
    const float sz = out[3 * q + 2];
    const float s2 = __fadd_rn(__fadd_rn(__fmul_rn(sx, sx), __fmul_rn(sy, sy)),
                               __fmul_rn(sz, sz));

    float kval = 3.4e38f;   // sorted ascending across lanes 0..15
    int   kidx = 0;
    float tau  = 3.4e38f;

    for (int t0 = 0; t0 < NPTS / TILEPTS; t0++) {
        __syncthreads();
        for (int j = threadIdx.x; j < TILEPTS; j += 256) {
            int g = t0 * TILEPTS + j;
            float a = p[3 * g + 0];
            float b = p[3 * g + 1];
            float c = p[3 * g + 2];
            float n2 = __fadd_rn(__fadd_rn(__fmul_rn(a, a), __fmul_rn(b, b)),
                                 __fmul_rn(c, c));
            tile[j] = make_float4(a, b, c, n2);
        }
        __syncthreads();

        for (int s = 0; s < TILEPTS / 32; s++) {
            float4 cd = tile[s * 32 + lane];
            float dot = __fadd_rn(__fadd_rn(__fmul_rn(sx, cd.x), __fmul_rn(sy, cd.y)),
                                  __fmul_rn(sz, cd.z));
            float key = __fsub_rn(__fadd_rn(s2, cd.w), __fmul_rn(2.0f, dot));

            unsigned mask = __ballot_sync(0xffffffffu, key < tau);
            while (mask) {
                int src = __ffs(mask) - 1;
                mask &= mask - 1;
                float v = __shfl_sync(0xffffffffu, key, src);
                if (v < tau) {
                    int id = t0 * TILEPTS + s * 32 + src;
                    bool ins = (lane < 16) && (v < kval);
                    float pv = __shfl_up_sync(0xffffffffu, kval, 1);
                    int   pi = __shfl_up_sync(0xffffffffu, kidx, 1);
                    int   pp = __shfl_up_sync(0xffffffffu, (int)ins, 1);
                    if (ins) {
                        bool useprev = (lane > 0) && pp;
                        kval = useprev ? pv : v;
                        kidx = useprev ? pi : id;
                    }
                    tau = __shfl_sync(0xffffffffu, kval, 15);
                }
            }
        }
    }

    float pjx = -3.4e38f, pjy = -3.4e38f, pjz = -3.4e38f, nrm = -3.4e38f;
    if (lane < 16) {
        int nb = kidx;
        pjx = p[3 * nb + 0] - sx;
        pjy = p[3 * nb + 1] - sy;
        pjz = p[3 * nb + 2] - sz;
        nrm = sqrtf(fmaf(pjz, pjz, fmaf(pjy, pjy, pjx * pjx)));
    }
    float mx = warpmaxf(nrm);
    float denom = mx + 1e-8f;
    float f0 = warpmaxf(pjx) / denom;
    float f1 = warpmaxf(pjy) / denom;
    float f2 = warpmaxf(pjz) / denom;

    float fx0 = -3.4e38f, fx1 = -3.4e38f;
#pragma unroll
    for (int j = 0; j < KNN; j++) {
        int row = __shfl_sync(0xffffffffu, kidx, j);
        const float* xr = x + row * DIN;
        fx0 = fmaxf(fx0, xr[lane]);
        fx1 = fmaxf(fx1, xr[lane + 32]);
    }

    const int c0 = lane, c1 = lane + 32, c2 = lane + 64, c3 = lane + 96;
    float a0 = bias[c0], a1 = bias[c1], a2 = bias[c2], a3 = bias[c3];
    {
        const float* w0 = W;
        const float* w1 = W + DOUT;
        const float* w2 = W + 2 * DOUT;
        a0 = fmaf(f0, w0[c0], a0); a1 = fmaf(f0, w0[c1], a1);
        a2 = fmaf(f0, w0[c2], a2); a3 = fmaf(f0, w0[c3], a3);
        a0 = fmaf(f1, w1[c0], a0); a1 = fmaf(f1, w1[c1], a1);
        a2 = fmaf(f1, w1[c2], a2); a3 = fmaf(f1, w1[c3], a3);
        a0 = fmaf(f2, w2[c0], a0); a1 = fmaf(f2, w2[c1], a1);
        a2 = fmaf(f2, w2[c2], a2); a3 = fmaf(f2, w2[c3], a3);
    }
#pragma unroll
    for (int r = 0; r < DIN; r++) {
        float fr = (r < 32) ? __shfl_sync(0xffffffffu, fx0, r)
                            : __shfl_sync(0xffffffffu, fx1, r - 32);
        const float* wr = W + (r + 3) * DOUT;
        a0 = fmaf(fr, wr[c0], a0);
        a1 = fmaf(fr, wr[c1], a1);
        a2 = fmaf(fr, wr[c2], a2);
        a3 = fmaf(fr, wr[c3], a3);
    }
    float* hq = g_h + q * DOUT;
    hq[c0] = a0; hq[c1] = a1; hq[c2] = a2; hq[c3] = a3;
}

// =====================================================================
// Kernel 3: BatchNorm statistics (deterministic two-pass)
// =====================================================================
__global__ __launch_bounds__(256)
void bn_stats_kernel(const float* __restrict__ gamma,
                     const float* __restrict__ beta)
{
    __shared__ float red[256];
    const int c = blockIdx.x;
    const int t = threadIdx.x;

    float s = 0.0f;
    for (int r = t; r < MPTS; r += 256) s += g_h[r * DOUT + c];
    red[t] = s;
    __syncthreads();
#pragma unroll
    for (int o = 128; o > 0; o >>= 1) {
        if (t < o) red[t] += red[t + o];
        __syncthreads();
    }
    float mean = red[0] * (1.0f / MPTS);
    __syncthreads();

    float s2 = 0.0f;
    for (int r = t; r < MPTS; r += 256) {
        float d = g_h[r * DOUT + c] - mean;
        s2 = fmaf(d, d, s2);
    }
    red[t] = s2;
    __syncthreads();
#pragma unroll
    for (int o = 128; o > 0; o >>= 1) {
        if (t < o) red[t] += red[t + o];
        __syncthreads();
    }
    if (t == 0) {
        float var = red[0] * (1.0f / MPTS);
        float sc = gamma[c] / sqrtf(var + 1e-5f);
        g_scale[c] = sc;
        g_shift[c] = beta[c] - mean * sc;
    }
}

// =====================================================================
// Kernel 4: normalize + ReLU + write x_out; write n_o tail
// =====================================================================
__global__ __launch_bounds__(256)
void finalize_kernel(float* __restrict__ out, int out_size)
{
    int i = blockIdx.x * 256 + threadIdx.x;
    if (i < MPTS * DOUT) {
        int c = i & (DOUT - 1);
        float v = fmaf(g_h[i], g_scale[c], g_shift[c]);
        out[3 * MPTS + i] = v > 0.0f ? v : 0.0f;
    }
    if (blockIdx.x == 0 && threadIdx.x == 0) {
        for (int j = 3 * MPTS + MPTS * DOUT; j < out_size; j++)
            out[j] = (float)MPTS;   // n_o = [M]
    }
}

// =====================================================================
extern "C" void kernel_launch(void* const* d_in, const int* in_sizes, int n_in,
                              void* d_out, int out_size)
{
    const float* p     = (const float*)d_in[0];
    const float* x     = (const float*)d_in[1];
    // d_in[2] = o (offsets), unused for single cloud
    const float* W     = (const float*)d_in[3];
    const float* b     = (const float*)d_in[4];
    const float* gamma = (const float*)d_in[5];
    const float* beta  = (const float*)d_in[6];
    float* out = (float*)d_out;

    const int smem = 3 * NPTS * 4 + NPTS * 2 + 512 * 4;  // coords + sid + hist
    cudaFuncSetAttribute((const void*)fps_kernel,
                         cudaFuncAttributeMaxDynamicSharedMemorySize, smem);

    fps_kernel<<<1, 1024, smem>>>(p, out);
    knn_feat_kernel<<<MPTS / 8, 256>>>(p, x, W, b, out);
    bn_stats_kernel<<<DOUT, 256>>>(gamma, beta);
    finalize_kernel<<<(MPTS * DOUT + 255) / 256, 256>>>(out, out_size);
}